// round 6
// baseline (speedup 1.0000x reference)
#include <cuda_runtime.h>
#include <cuda_fp16.h>
#include <cstdint>

// ---------------- model constants ----------------
#define BSZ      512
#define NCH      129
#define NT       250
#define DINNER   256
#define DSTATE   16
#define NHEADS   4
#define CONVDIM  288
#define DPROJ    548
#define EPSV     1e-5f

// GEMM tiling: K = 128 (MMA) + 1 (rank-1 epilogue fixup)
#define TM     128
#define TN     72
#define TK     128
#define NJC    8
#define NKK    8
#define PITCHB 272
#define SPITCH 76

// scan tiling
#define TT     15         // timesteps per tile (17 tiles: 16x15 + 10)

// ---------------- device scratch ----------------
__device__ float g_W[DPROJ * NCH];
__device__ float g_bias[DPROJ];
__device__ float g_v[DINNER];
__device__ float g_zxbcdt[(size_t)BSZ * NT * DPROJ];
__device__ __align__(16) __half g_Wh[NJC * TN * TK];
__device__ float g_Wcol[576];
__device__ float g_biasP[576];

// ---------------- GEMM smem layout (bytes) ----------------
#define SM_AHI   0
#define SM_ALO   34816
#define SM_BH    69632
#define SM_X128  89216
#define SM_W128  89728
#define SM_BIAS  90016
#define SMEM_SZ  90304

// ---------------- scan smem layout (bytes) ----------------
#define SC_XBC   0                        // TT*288*4   = 17280
#define SC_CS    17280                    // TT*128*8   = 15360
#define SC_GZ    32640                    // 15360
#define SC_B2    48000                    // TT*16*8    = 1920
#define SC_C2    49920                    // 1920
#define SC_DA    51840                    // TT*4*4     = 240
#define SC_DT    52080                    // 240
#define SC_PS    52320                    // TT*4*8     = 480
#define SC_SZ    52832

// ---------------- packed f32x2 helpers ----------------
typedef unsigned long long ull;
__device__ __forceinline__ ull dup2(float v) {
    ull r; asm("mov.b64 %0, {%1, %1};" : "=l"(r) : "f"(v)); return r;
}
__device__ __forceinline__ ull pack2(float lo, float hi) {
    ull r; asm("mov.b64 %0, {%1, %2};" : "=l"(r) : "f"(lo), "f"(hi)); return r;
}
__device__ __forceinline__ ull ffma2(ull a, ull b, ull c) {
    ull d; asm("fma.rn.f32x2 %0, %1, %2, %3;" : "=l"(d) : "l"(a), "l"(b), "l"(c)); return d;
}
__device__ __forceinline__ ull fmul2(ull a, ull b) {
    ull d; asm("mul.rn.f32x2 %0, %1, %2;" : "=l"(d) : "l"(a), "l"(b)); return d;
}
__device__ __forceinline__ ull fadd2(ull a, ull b) {
    ull d; asm("add.rn.f32x2 %0, %1, %2;" : "=l"(d) : "l"(a), "l"(b)); return d;
}
__device__ __forceinline__ float2 unpk2(ull v) {
    float2 f; asm("mov.b64 {%0, %1}, %2;" : "=f"(f.x), "=f"(f.y) : "l"(v)); return f;
}

// ---------------- mma / ldmatrix (base sm_103 PTX) ----------------
__device__ __forceinline__ void mma16816(float* d, const uint32_t* a, const uint32_t* b) {
    asm volatile(
        "mma.sync.aligned.m16n8k16.row.col.f32.f16.f16.f32 "
        "{%0,%1,%2,%3}, {%4,%5,%6,%7}, {%8,%9}, {%0,%1,%2,%3};"
        : "+f"(d[0]), "+f"(d[1]), "+f"(d[2]), "+f"(d[3])
        : "r"(a[0]), "r"(a[1]), "r"(a[2]), "r"(a[3]), "r"(b[0]), "r"(b[1]));
}
__device__ __forceinline__ void ldsm4(uint32_t* r, uint32_t addr) {
    asm volatile("ldmatrix.sync.aligned.m8n8.x4.shared.b16 {%0,%1,%2,%3}, [%4];"
        : "=r"(r[0]), "=r"(r[1]), "=r"(r[2]), "=r"(r[3]) : "r"(addr));
}
__device__ __forceinline__ void ldsm2(uint32_t* r, uint32_t addr) {
    asm volatile("ldmatrix.sync.aligned.m8n8.x2.shared.b16 {%0,%1}, [%2];"
        : "=r"(r[0]), "=r"(r[1]) : "r"(addr));
}
__device__ __forceinline__ uint32_t smem_u32(const void* p) {
    uint32_t a;
    asm("{ .reg .u64 t; cvta.to.shared.u64 t, %1; cvt.u32.u64 %0, t; }" : "=r"(a) : "l"(p));
    return a;
}

// =====================================================================
// prep1: fused weights
// =====================================================================
__global__ void prep1_kernel(const float* __restrict__ in_proj_w,
                             const float* __restrict__ mixer_w,
                             const float* __restrict__ mixer_b,
                             const float* __restrict__ out_proj_w,
                             const float* __restrict__ head_w) {
    int idx = blockIdx.x * blockDim.x + threadIdx.x;
    const int NW = DPROJ * NCH;
    if (idx < NW) {
        int j = idx / NCH, c = idx - j * NCH;
        float a0 = 0.f, a1 = 0.f, a2 = 0.f, a3 = 0.f;
        #pragma unroll 8
        for (int d = 0; d < 128; d += 4) {
            a0 = fmaf(in_proj_w[j * 128 + d + 0], mixer_w[(d + 0) * NCH + c], a0);
            a1 = fmaf(in_proj_w[j * 128 + d + 1], mixer_w[(d + 1) * NCH + c], a1);
            a2 = fmaf(in_proj_w[j * 128 + d + 2], mixer_w[(d + 2) * NCH + c], a2);
            a3 = fmaf(in_proj_w[j * 128 + d + 3], mixer_w[(d + 3) * NCH + c], a3);
        }
        g_W[idx] = (a0 + a1) + (a2 + a3);
    } else if (idx < NW + DPROJ) {
        int j = idx - NW;
        float acc = 0.f;
        #pragma unroll 4
        for (int d = 0; d < 128; d++)
            acc = fmaf(in_proj_w[j * 128 + d], mixer_b[d], acc);
        g_bias[j] = acc;
    } else if (idx < NW + DPROJ + DINNER) {
        int i = idx - NW - DPROJ;
        float acc = 0.f;
        #pragma unroll 4
        for (int d = 0; d < 128; d++)
            acc = fmaf(out_proj_w[d * DINNER + i], head_w[d], acc);
        g_v[i] = acc;
    }
}

// =====================================================================
// prep2: W (k<128) -> fp16 chunk tiles; pad Wcol/bias
// =====================================================================
__global__ void prep2_kernel() {
    int idx = blockIdx.x * blockDim.x + threadIdx.x;
    const int NH = NJC * TN * TK;
    if (idx < NH) {
        int k = idx & 127;
        int t = idx >> 7;
        int n = t % TN;
        int jc = t / TN;
        int j = jc * TN + n;
        float val = (j < DPROJ) ? g_W[j * NCH + k] : 0.f;
        g_Wh[idx] = __float2half(val);
    } else if (idx < NH + 576) {
        int j = idx - NH;
        g_Wcol[j] = (j < DPROJ) ? g_W[j * NCH + 128] : 0.f;
    } else if (idx < NH + 1152) {
        int j = idx - NH - 576;
        g_biasP[j] = (j < DPROJ) ? g_bias[j] : 0.f;
    }
}

// =====================================================================
// gemm_mma: 2-pass fp16 split GEMM (unchanged from R5 — at HMMA floor)
// =====================================================================
__global__ void __launch_bounds__(256, 2) gemm_mma(const float* __restrict__ x) {
    extern __shared__ __align__(16) unsigned char sm[];
    const uint32_t sbase = smem_u32(sm);
    const int tid = threadIdx.x;
    const int wid = tid >> 5, lane = tid & 31;
    const int gid = lane >> 2, tig = lane & 3;
    const int tt = blockIdx.x, jc = blockIdx.y, b = blockIdx.z;
    const int t0 = tt * TM;

    {
        const unsigned char* src = (const unsigned char*)(g_Wh + (size_t)jc * (TN * TK));
        for (int i = tid; i < TN * 16; i += 256) {
            int n = i >> 4, q = i & 15;
            *(uint4*)(sm + SM_BH + n * PITCHB + q * 16) = *(const uint4*)(src + n * 256 + q * 16);
        }
    }
    {
        const float* xb = x + (size_t)b * (NCH * NT);
        for (int i = tid; i < 64 * TM; i += 256) {
            int cp = i >> 7, m = i & (TM - 1);
            int t = t0 + m;
            int c0 = 2 * cp;
            float v0 = (t < NT) ? xb[(size_t)c0 * NT + t] : 0.f;
            float v1 = (t < NT) ? xb[(size_t)(c0 + 1) * NT + t] : 0.f;
            __half h0 = __float2half(v0), h1 = __float2half(v1);
            __half l0 = __float2half(v0 - __half2float(h0));
            __half l1 = __float2half(v1 - __half2float(h1));
            uint32_t off = (uint32_t)m * PITCHB + (uint32_t)cp * 4;
            *(__half2*)(sm + SM_AHI + off) = __half2{h0, h1};
            *(__half2*)(sm + SM_ALO + off) = __half2{l0, l1};
        }
    }
    if (tid < 128) {
        int t = t0 + tid;
        const float* xb = x + (size_t)b * (NCH * NT);
        *(float*)(sm + SM_X128 + tid * 4) = (t < NT) ? xb[(size_t)128 * NT + t] : 0.f;
        if (tid < TN) {
            *(float*)(sm + SM_W128 + tid * 4) = g_Wcol[jc * TN + tid];
            *(float*)(sm + SM_BIAS + tid * 4) = g_biasP[jc * TN + tid];
        }
    }
    __syncthreads();

    float acc[9][4];
    #pragma unroll
    for (int ni = 0; ni < 9; ni++)
        #pragma unroll
        for (int q = 0; q < 4; q++) acc[ni][q] = 0.f;

    const uint32_t aOff = (uint32_t)(wid * 16 + (lane & 15)) * PITCHB + (uint32_t)(lane >> 4) * 16;
    const uint32_t bOff = (uint32_t)(lane & 15) * PITCHB + (uint32_t)(lane >> 4) * 16;
    const uint32_t b2Off = (uint32_t)(64 + (lane & 7)) * PITCHB + (uint32_t)((lane >> 3) & 1) * 16;

    const uint32_t Ah = sbase + SM_AHI + aOff;
    const uint32_t Al = sbase + SM_ALO + aOff;
    const uint32_t Bb = sbase + SM_BH + bOff;
    const uint32_t Bb2 = sbase + SM_BH + b2Off;

    #pragma unroll
    for (int kk = 0; kk < NKK; kk++) {
        uint32_t ah[4], al[4];
        ldsm4(ah, Ah + kk * 32);
        ldsm4(al, Al + kk * 32);
        #pragma unroll
        for (int q = 0; q < 4; q++) {
            uint32_t bb[4];
            ldsm4(bb, Bb + (uint32_t)(q * 16) * PITCHB + kk * 32);
            uint32_t f0[2] = { bb[0], bb[2] };
            uint32_t f1[2] = { bb[1], bb[3] };
            mma16816(acc[2 * q],     ah, f0);
            mma16816(acc[2 * q],     al, f0);
            mma16816(acc[2 * q + 1], ah, f1);
            mma16816(acc[2 * q + 1], al, f1);
        }
        uint32_t b2[2];
        ldsm2(b2, Bb2 + kk * 32);
        mma16816(acc[8], ah, b2);
        mma16816(acc[8], al, b2);
    }

    __syncthreads();
    float* stage = (float*)sm;
    {
        int r = wid * 16 + gid;
        #pragma unroll
        for (int ni = 0; ni < 9; ni++) {
            int c = ni * 8 + 2 * tig;
            *(float2*)(stage + r * SPITCH + c) = make_float2(acc[ni][0], acc[ni][1]);
            *(float2*)(stage + (r + 8) * SPITCH + c) = make_float2(acc[ni][2], acc[ni][3]);
        }
    }
    __syncthreads();

    const float* xs128 = (const float*)(sm + SM_X128);
    const float* sW = (const float*)(sm + SM_W128);
    const float* sBs = (const float*)(sm + SM_BIAS);
    for (int i = tid; i < TM * (TN / 4); i += 256) {
        int row = i / (TN / 4), q = i % (TN / 4);
        int t = t0 + row;
        int j = jc * TN + 4 * q;
        if (t < NT && j + 3 < DPROJ) {
            const float* sp = stage + row * SPITCH + 4 * q;
            float xk = xs128[row];
            float4 o;
            o.x = fmaf(xk, sW[4 * q + 0], sp[0] + sBs[4 * q + 0]);
            o.y = fmaf(xk, sW[4 * q + 1], sp[1] + sBs[4 * q + 1]);
            o.z = fmaf(xk, sW[4 * q + 2], sp[2] + sBs[4 * q + 2]);
            o.w = fmaf(xk, sW[4 * q + 3], sp[3] + sBs[4 * q + 3]);
            *(float4*)(g_zxbcdt + ((size_t)b * NT + t) * DPROJ + j) = o;
        }
    }
}

// =====================================================================
// scan: tiled two-phase scan (15 steps/tile)
//   Phase A (parallel): bulk loads + conv + silu + softplus -> smem
//   Phase B (sequential): 15 steps, no barriers, no global access
//   roles: tid<128 scan+conv(ch 2tid,2tid+1); 128-143 conv B/C;
//          144-159 dt for timestep tid-144
// =====================================================================
__global__ void __launch_bounds__(160, 4)
scan_kernel(const float* __restrict__ conv_w, const float* __restrict__ conv_b,
            const float* __restrict__ dt_bias, const float* __restrict__ A_log,
            const float* __restrict__ Dp, const float* __restrict__ norm_w,
            const float* __restrict__ head_b, float* __restrict__ out) {
    extern __shared__ __align__(16) unsigned char smr[];
    float*  sXBC = (float*)(smr + SC_XBC);     // [TT][288]
    float2* sCS  = (float2*)(smr + SC_CS);     // [TT][128]
    float2* sGZ  = (float2*)(smr + SC_GZ);     // [TT][128]
    ull*    sB2  = (ull*)(smr + SC_B2);        // [TT][16] dup pairs
    ull*    sC2  = (ull*)(smr + SC_C2);
    float*  sDA  = (float*)(smr + SC_DA);      // [TT][4]
    float*  sDT  = (float*)(smr + SC_DT);
    float2* sPS  = (float2*)(smr + SC_PS);     // [TT][4]

    const int b = blockIdx.x;
    const int tid = threadIdx.x;
    const int lane = tid & 31, wid = tid >> 5;
    const int c0 = 2 * tid;
    const int h = tid >> 5;                    // head for scan threads

    const bool isConv = (tid < 144);
    const bool isScan = (tid < 128);
    const bool isDt   = (tid >= 144);

    // conv params (2 channels packed)
    ull wk0 = 0, wk1 = 0, wk2_ = 0, wk3 = 0, cb2 = 0;
    if (isConv) {
        wk0 = pack2(conv_w[c0 * 4 + 0], conv_w[(c0 + 1) * 4 + 0]);
        wk1 = pack2(conv_w[c0 * 4 + 1], conv_w[(c0 + 1) * 4 + 1]);
        wk2_ = pack2(conv_w[c0 * 4 + 2], conv_w[(c0 + 1) * 4 + 2]);
        wk3 = pack2(conv_w[c0 * 4 + 3], conv_w[(c0 + 1) * 4 + 3]);
        cb2 = pack2(conv_b[c0], conv_b[c0 + 1]);
    }
    ull hh1 = 0ULL, hh2 = 0ULL, hh3 = 0ULL;    // conv history

    float nw0 = 0.f, nw1 = 0.f; ull D2 = 0ULL;
    if (isScan) {
        nw0 = norm_w[c0] * g_v[c0];
        nw1 = norm_w[c0 + 1] * g_v[c0 + 1];
        D2 = dup2(Dp[h]);
    }
    float dtb[NHEADS], An[NHEADS];
    if (isDt) {
        #pragma unroll
        for (int q = 0; q < NHEADS; q++) {
            dtb[q] = dt_bias[q];
            An[q] = -expf(A_log[q]);
        }
    }

    ull s2[DSTATE];
    #pragma unroll
    for (int n = 0; n < DSTATE; n++) s2[n] = 0ULL;
    float facc = 0.f;

    const float* row = g_zxbcdt + (size_t)b * NT * DPROJ;

    for (int t0 = 0; t0 < NT; t0 += TT) {
        const int tc = (NT - t0 < TT) ? (NT - t0) : TT;

        // ---- Phase A0: bulk loads ----
        for (int i = tid; i < tc * 72; i += 160) {
            int tt = i / 72, q = i % 72;
            *(uint4*)(sXBC + tt * 288 + 4 * q) =
                *(const uint4*)(row + (size_t)(t0 + tt) * DPROJ + DINNER + 4 * q);
        }
        if (isScan) {
            #pragma unroll 5
            for (int tt = 0; tt < tc; tt++) {
                float2 z = *(const float2*)(row + (size_t)(t0 + tt) * DPROJ + c0);
                float g0 = __fdividef(z.x, 1.f + __expf(-z.x));
                float g1 = __fdividef(z.y, 1.f + __expf(-z.y));
                sGZ[tt * 128 + tid] = make_float2(g0, g1);
            }
        }
        if (isDt) {
            int tt = tid - 144;
            if (tt < tc) {
                float4 d4 = *(const float4*)(row + (size_t)(t0 + tt) * DPROJ + (DPROJ - NHEADS));
                float dv[4] = { d4.x, d4.y, d4.z, d4.w };
                #pragma unroll
                for (int q = 0; q < NHEADS; q++) {
                    float rv = dv[q] + dtb[q];
                    float dtv = (rv > 15.f) ? rv : __logf(1.f + __expf(rv));
                    sDT[tt * 4 + q] = dtv;
                    sDA[tt * 4 + q] = __expf(dtv * An[q]);
                }
            }
        }
        __syncthreads();   // B1: sXBC ready

        // ---- Phase A1: conv + silu ----
        if (isConv) {
            for (int tt = 0; tt < tc; tt++) {
                ull raw2 = *(const ull*)(sXBC + tt * 288 + c0);
                ull cv2 = ffma2(wk3, raw2, ffma2(wk2_, hh1, ffma2(wk1, hh2, ffma2(wk0, hh3, cb2))));
                hh3 = hh2; hh2 = hh1; hh1 = raw2;
                float2 cv = unpk2(cv2);
                float cs0 = __fdividef(cv.x, 1.f + __expf(-cv.x));
                float cs1 = __fdividef(cv.y, 1.f + __expf(-cv.y));
                if (tid < 128) {
                    sCS[tt * 128 + tid] = make_float2(cs0, cs1);
                } else if (tid < 136) {
                    sB2[tt * 16 + 2 * (tid - 128)]     = dup2(cs0);
                    sB2[tt * 16 + 2 * (tid - 128) + 1] = dup2(cs1);
                } else {
                    sC2[tt * 16 + 2 * (tid - 136)]     = dup2(cs0);
                    sC2[tt * 16 + 2 * (tid - 136) + 1] = dup2(cs1);
                }
            }
        }
        __syncthreads();   // B2: cs/B/C/dt ready

        // ---- Phase B: sequential scan, no barriers ----
        if (isScan) {
            for (int tt = 0; tt < tc; tt++) {
                float2 cs = sCS[tt * 128 + tid];
                float2 gz = sGZ[tt * 128 + tid];
                float dAv = sDA[tt * 4 + h];
                float dtv = sDT[tt * 4 + h];
                ull dA2 = dup2(dAv);
                ull dx2 = pack2(dtv * cs.x, dtv * cs.y);
                ull cs2 = pack2(cs.x, cs.y);
                ull ya = fmul2(D2, cs2);
                ull yb = 0ULL;
                const ull* Bt = sB2 + tt * 16;
                const ull* Ct = sC2 + tt * 16;
                #pragma unroll
                for (int n = 0; n < DSTATE; n += 2) {
                    s2[n]     = ffma2(s2[n],     dA2, fmul2(dx2, Bt[n]));
                    ya        = ffma2(s2[n],     Ct[n], ya);
                    s2[n + 1] = ffma2(s2[n + 1], dA2, fmul2(dx2, Bt[n + 1]));
                    yb        = ffma2(s2[n + 1], Ct[n + 1], yb);
                }
                float2 yy = unpk2(fadd2(ya, yb));
                float g0 = yy.x * gz.x;
                float g1 = yy.y * gz.y;
                float ss = fmaf(g0, g0, g1 * g1);
                float p  = fmaf(g0, nw0, g1 * nw1);
                #pragma unroll
                for (int o = 16; o > 0; o >>= 1) {
                    ss += __shfl_xor_sync(0xffffffffu, ss, o);
                    p  += __shfl_xor_sync(0xffffffffu, p, o);
                }
                if (lane == 0) sPS[tt * 4 + wid] = make_float2(ss, p);
            }
        }
        __syncthreads();   // B3: sPS ready

        // ---- tile finalize: deferred rsqrt ----
        if (tid < tc) {
            float2 a = sPS[tid * 4 + 0], b2 = sPS[tid * 4 + 1];
            float2 c = sPS[tid * 4 + 2], d = sPS[tid * 4 + 3];
            float SS = (a.x + b2.x) + (c.x + d.x);
            float P  = (a.y + b2.y) + (c.y + d.y);
            facc = fmaf(P, rsqrtf(SS * (1.f / 256.f) + EPSV), facc);
        }
        // no barrier needed: sPS next written only after next B2
    }

    // facc lives on warp 0 lanes 0..TT-1 (others zero)
    #pragma unroll
    for (int o = 16; o > 0; o >>= 1) facc += __shfl_xor_sync(0xffffffffu, facc, o);
    if (tid == 0) out[b] = facc * (1.f / (float)NT) + head_b[0];
}

// =====================================================================
// launch
// =====================================================================
extern "C" void kernel_launch(void* const* d_in, const int* in_sizes, int n_in,
                              void* d_out, int out_size) {
    const float* x          = (const float*)d_in[0];
    const float* mixer_w    = (const float*)d_in[1];
    const float* mixer_b    = (const float*)d_in[2];
    const float* in_proj_w  = (const float*)d_in[3];
    const float* conv_w     = (const float*)d_in[4];
    const float* conv_b     = (const float*)d_in[5];
    const float* dt_bias    = (const float*)d_in[6];
    const float* A_log      = (const float*)d_in[7];
    const float* Dvec       = (const float*)d_in[8];
    const float* norm_w     = (const float*)d_in[9];
    const float* out_proj_w = (const float*)d_in[10];
    const float* head_w     = (const float*)d_in[11];
    const float* head_b     = (const float*)d_in[12];
    float* out = (float*)d_out;

    {
        int total = DPROJ * NCH + DPROJ + DINNER;
        prep1_kernel<<<(total + 255) / 256, 256>>>(in_proj_w, mixer_w, mixer_b,
                                                   out_proj_w, head_w);
    }
    {
        int total = NJC * TN * TK + 1152;
        prep2_kernel<<<(total + 255) / 256, 256>>>();
    }
    {
        cudaFuncSetAttribute(gemm_mma,
                             cudaFuncAttributeMaxDynamicSharedMemorySize, SMEM_SZ);
        dim3 grid(2, NJC, BSZ);
        gemm_mma<<<grid, 256, SMEM_SZ>>>(x);
    }
    {
        cudaFuncSetAttribute(scan_kernel,
                             cudaFuncAttributeMaxDynamicSharedMemorySize, SC_SZ);
        scan_kernel<<<BSZ, 160, SC_SZ>>>(conv_w, conv_b, dt_bias, A_log, Dvec,
                                         norm_w, head_b, out);
    }
}